// round 8
// baseline (speedup 1.0000x reference)
#include <cuda_runtime.h>
#include <cstdint>

#define L2E 1.4426950408889634f
#define BATCH 64
#define SEQ 512
#define HID 768
#define NC 21
#define NCP 24
#define EM_STRIDE (SEQ * NC)   // 10752 floats per batch

__device__ __align__(16) float g_emx[BATCH * SEQ * NC];  // 2^em2 (linear emissions)
__device__ __align__(16) float g_wl2e[HID * NCP];        // W * log2e, padded to 24 cols
__device__ float g_res[BATCH];                           // per-batch (logZ2 - num2)

__device__ __forceinline__ float fast_ex2(float x) {
    float y; asm("ex2.approx.ftz.f32 %0, %1;" : "=f"(y) : "f"(x)); return y;
}
__device__ __forceinline__ float fast_lg2(float x) {
    float y; asm("lg2.approx.ftz.f32 %0, %1;" : "=f"(y) : "f"(x)); return y;
}
#define FFMA2(acc, a, b) \
    asm("fma.rn.f32x2 %0, %1, %2, %3;" : "=l"(acc) : "l"(a), "l"(b), "l"(acc))

// ---------------------------------------------------------------------------
// Kernel 0: pad + pre-scale W into g_wl2e[768][24] (16B-aligned rows so the
// gemm can read 12-col halves as LDG.128; cols 21..23 are zero).
// ---------------------------------------------------------------------------
__global__ void pad_w_kernel(const float* __restrict__ W) {
    int idx = blockIdx.x * blockDim.x + threadIdx.x;
    if (idx < HID * NCP) {
        int kk = idx / NCP, c = idx - kk * NCP;
        g_wl2e[idx] = (c < NC) ? W[kk * NC + c] * L2E : 0.f;
    }
}

// ---------------------------------------------------------------------------
// Kernel 1: emissions GEMM — registers only, NO smem staging, NO barriers in
// the main loop. R7's smem pipeline staged hidden through smem although each
// 32B chunk feeds exactly one thread; that lockstep was the 52us wall.
// hidden: __ldcs float4 direct to regs (evict-first). W: L1-resident LDG.128
// broadcasts from g_wl2e (74KB, hot per SM). 512 blocks x 256 threads, BM=64.
// thread = (m2 = tid&31 -> rows {m2, m2+32}, half -> 12 cols, ks -> 8 of 32 kk)
// 4-way K-split merged via smem at the very end (2 barriers total).
// ---------------------------------------------------------------------------
__global__ __launch_bounds__(256, 3) void gemm_kernel(
    const float* __restrict__ hidden,
    const float* __restrict__ bias)
{
    __shared__ __align__(16) uint64_t mrg[64][3][12];    // 18 KB merge only

    const int tid  = threadIdx.x;
    const int m2   = tid & 31;
    const int half = (tid >> 5) & 1;
    const int ks   = tid >> 6;           // 0..3
    const int grp  = tid & 63;
    const int row0 = blockIdx.x * 64;

    const float* hr0 = hidden + (row0 + m2) * HID;
    const float* hr1 = hidden + (row0 + m2 + 32) * HID;
    const float* wbase = g_wl2e + half * 12;

    uint64_t acc[2][6];
#pragma unroll
    for (int r = 0; r < 2; r++)
#pragma unroll
        for (int i = 0; i < 6; i++) acc[r][i] = 0ull;

    const int kklo = ks * 8;
#pragma unroll 4
    for (int it = 0; it < 24; it++) {
        const int base = it * 32 + kklo;
        float4 a0 = __ldcs((const float4*)(hr0 + base));
        float4 a1 = __ldcs((const float4*)(hr0 + base + 4));
        float4 b0 = __ldcs((const float4*)(hr1 + base));
        float4 b1 = __ldcs((const float4*)(hr1 + base + 4));
        float ha[8] = {a0.x, a0.y, a0.z, a0.w, a1.x, a1.y, a1.z, a1.w};
        float hb[8] = {b0.x, b0.y, b0.z, b0.w, b1.x, b1.y, b1.z, b1.w};
#pragma unroll
        for (int kkk = 0; kkk < 8; kkk++) {
            const ulonglong2* wp =
                reinterpret_cast<const ulonglong2*>(wbase + (base + kkk) * NCP);
            ulonglong2 q0 = wp[0], q1 = wp[1], q2 = wp[2];
            uint64_t h0x, h1x;
            asm("mov.b64 %0, {%1, %1};" : "=l"(h0x) : "f"(ha[kkk]));
            asm("mov.b64 %0, {%1, %1};" : "=l"(h1x) : "f"(hb[kkk]));
            FFMA2(acc[0][0], h0x, q0.x); FFMA2(acc[0][1], h0x, q0.y);
            FFMA2(acc[0][2], h0x, q1.x); FFMA2(acc[0][3], h0x, q1.y);
            FFMA2(acc[0][4], h0x, q2.x); FFMA2(acc[0][5], h0x, q2.y);
            FFMA2(acc[1][0], h1x, q0.x); FFMA2(acc[1][1], h1x, q0.y);
            FFMA2(acc[1][2], h1x, q1.x); FFMA2(acc[1][3], h1x, q1.y);
            FFMA2(acc[1][4], h1x, q2.x); FFMA2(acc[1][5], h1x, q2.y);
        }
    }

    // merge 4-way K-split partials, apply bias, write emx (linear only)
    if (ks != 0) {
#pragma unroll
        for (int r = 0; r < 2; r++)
#pragma unroll
            for (int i = 0; i < 6; i++) mrg[grp][ks - 1][r * 6 + i] = acc[r][i];
    }
    __syncthreads();
    if (ks == 0) {
        const int cb = half * 12;
#pragma unroll
        for (int r = 0; r < 2; r++) {
            const int out_base = (row0 + m2 + r * 32) * NC;
#pragma unroll
            for (int p = 0; p < 6; p++) {
                uint64_t sum = acc[r][p];
#pragma unroll
                for (int q = 0; q < 3; q++) {
                    uint64_t o = mrg[grp][q][r * 6 + p];
                    asm("add.rn.f32x2 %0, %1, %2;" : "=l"(sum) : "l"(sum), "l"(o));
                }
                float2 f = *reinterpret_cast<float2*>(&sum);
                int c = cb + 2 * p;
                if (c < NC)
                    g_emx[out_base + c]     = fast_ex2(f.x + bias[c] * L2E);
                if (c + 1 < NC)
                    g_emx[out_base + c + 1] = fast_ex2(f.y + bias[c + 1] * L2E);
            }
        }
    }
}

// ---------------------------------------------------------------------------
// Kernel 2: per-batch CRF, linear-space scan, smem-broadcast alpha.
// R8: no emissions smem staging (per-lane emn LDGs software-prefetched 3 steps
// ahead; rows are L1/L2-hot); numerator recomputes log-emissions as
// lg2(emx) so g_em2 no longer exists.
// ---------------------------------------------------------------------------
__global__ __launch_bounds__(128) void crf_kernel(
    const float* __restrict__ start_t,
    const float* __restrict__ end_t,
    const float* __restrict__ trans,
    const int*   __restrict__ labr)
{
    __shared__ __align__(16) float av[2][24];
    __shared__ float red_f[128];
    __shared__ int   red_i[128];
    __shared__ float s_num2;
    __shared__ int   s_len;

    const int b   = blockIdx.x;
    const int tid = threadIdx.x;
    const float* emx_g = g_emx + b * EM_STRIDE;

    // labels dtype detection (int32 vs int64; reads in-bounds for both)
    int ok = 1;
    for (int t = tid; t < SEQ; t += 128) {
        int v = labr[2 * t + 1];
        if (v != 0 && v != -1) ok = 0;
    }
    int is64 = __syncthreads_and(ok);
    const int lbase = is64 ? b * SEQ * 2 : b * SEQ;
    const int lstep = is64 ? 2 : 1;
#define LAB(t) labr[lbase + (t) * lstep]

    // numerator (log2 domain) + valid length (mask is a prefix)
    float p = 0.f;
    int cnt = 0;
    for (int t = tid; t < SEQ; t += 128) {
        int l = LAB(t);
        if (l != -100) {
            cnt++;
            if (t == 0) {
                p += start_t[l] * L2E + fast_lg2(emx_g[l]);
            } else {
                int lp = LAB(t - 1);
                p += fast_lg2(emx_g[t * NC + l]) + trans[lp * NC + l] * L2E;
            }
        }
    }
    red_f[tid] = p;
    red_i[tid] = cnt;
    __syncthreads();
    for (int s = 64; s > 0; s >>= 1) {
        if (tid < s) { red_f[tid] += red_f[tid + s]; red_i[tid] += red_i[tid + s]; }
        __syncthreads();
    }
    if (tid == 0) {
        int len = red_i[0];
        s_len   = len;
        s_num2  = red_f[0] + end_t[LAB(len - 1)] * L2E;
    }
    __syncthreads();

    if (tid < 32) {
        const int lane = tid;
        const int j = lane < NC ? lane : NC - 1;
        float tl[24];
#pragma unroll
        for (int i = 0; i < NC; i++) tl[i] = fast_ex2(trans[i * NC + j] * L2E);
        tl[21] = tl[22] = tl[23] = 0.f;
        const float endx = fast_ex2(end_t[j] * L2E);
        const int len = s_len;

        float a = fast_ex2(start_t[j] * L2E) * emx_g[j];
        if (lane < NC)  av[0][lane] = a;
        if (lane >= NC && lane < 24) { av[0][lane] = 0.f; av[1][lane] = 0.f; }
        int offe = 0;
        int buf  = 0;

        // emn software prefetch pipeline (depth 3, L1/L2-hit latency)
        float emn1 = emx_g[1 * NC + j];
        float emn2 = (2 < len) ? emx_g[2 * NC + j] : 0.f;
        float emn3 = (3 < len) ? emx_g[3 * NC + j] : 0.f;

        for (int t = 1; t < len; t++) {
            __syncwarp();
            const float4* vp = reinterpret_cast<const float4*>(av[buf]);
            float4 v0 = vp[0], v1 = vp[1], v2 = vp[2],
                   v3 = vp[3], v4 = vp[4], v5 = vp[5];
            float emn_new = (t + 3 < len) ? emx_g[(t + 3) * NC + j] : 0.f;
            int   e     = ((__float_as_int(v0.x) >> 23) & 255) - 127;
            float sclem = __int_as_float((127 - e) << 23) * emn1;  // exact 2^-e
            offe += e;

            float s0 = v0.x * tl[0],  s1 = v0.y * tl[1],  s2 = v0.z * tl[2];
            float s3 = v0.w * tl[3],  s4 = v1.x * tl[4],  s5 = v1.y * tl[5];
            s0 += v1.z * tl[6];   s1 += v1.w * tl[7];   s2 += v2.x * tl[8];
            s3 += v2.y * tl[9];   s4 += v2.z * tl[10];  s5 += v2.w * tl[11];
            s0 += v3.x * tl[12];  s1 += v3.y * tl[13];  s2 += v3.z * tl[14];
            s3 += v3.w * tl[15];  s4 += v4.x * tl[16];  s5 += v4.y * tl[17];
            s0 += v4.z * tl[18];  s1 += v4.w * tl[19];  s2 += v5.x * tl[20];
            s3 += v5.y * tl[21];  s4 += v5.z * tl[22];  s5 += v5.w * tl[23];

            a = (((s0 + s1) + (s2 + s3)) + (s4 + s5)) * sclem;
            buf ^= 1;
            if (lane < NC) av[buf][lane] = a;
            emn1 = emn2; emn2 = emn3; emn3 = emn_new;
        }
        __syncwarp();

        float ex = (lane < NC) ? a * endx : 0.f;
#pragma unroll
        for (int d = 16; d > 0; d >>= 1)
            ex += __shfl_xor_sync(0xffffffffu, ex, d);
        if (lane == 0)
            g_res[b] = (float)offe + fast_lg2(ex) - s_num2;
    }
#undef LAB
}

// ---------------------------------------------------------------------------
__global__ void finish_kernel(float* __restrict__ out) {
    int tid = threadIdx.x;           // 32 threads
    float v = g_res[tid] + g_res[tid + 32];
#pragma unroll
    for (int d = 16; d > 0; d >>= 1)
        v += __shfl_xor_sync(0xffffffffu, v, d);
    if (tid == 0) out[0] = v * (1.0f / (64.0f * L2E));
}

// ---------------------------------------------------------------------------
extern "C" void kernel_launch(void* const* d_in, const int* in_sizes, int n_in,
                              void* d_out, int out_size)
{
    const float* hidden = nullptr;
    const float* W      = nullptr;
    const float* trans  = nullptr;
    const int*   labels = nullptr;
    const float* small[3] = {nullptr, nullptr, nullptr};
    int nsmall = 0;

    for (int i = 0; i < n_in; i++) {
        switch (in_sizes[i]) {
            case BATCH * SEQ * HID: hidden = (const float*)d_in[i]; break;
            case HID * NC:          W      = (const float*)d_in[i]; break;
            case NC * NC:           trans  = (const float*)d_in[i]; break;
            case BATCH * SEQ:       labels = (const int*)d_in[i];   break;
            case NC: if (nsmall < 3) small[nsmall++] = (const float*)d_in[i]; break;
            default: break;
        }
    }
    const float* bias    = small[0];
    const float* start_t = small[1];
    const float* end_t   = small[2];

    pad_w_kernel<<<(HID * NCP + 255) / 256, 256>>>(W);
    gemm_kernel<<<512, 256>>>(hidden, bias);
    crf_kernel<<<BATCH, 128>>>(start_t, end_t, trans, labels);
    finish_kernel<<<1, 32>>>((float*)d_out);
}

// round 10
// speedup vs baseline: 3.0938x; 3.0938x over previous
#include <cuda_runtime.h>
#include <cuda_bf16.h>
#include <cstdint>

#define L2E 1.4426950408889634f
#define BATCH 64
#define SEQ 512
#define HID 768
#define NC 21
#define EM_STRIDE (SEQ * NC)

#define BM 64
#define ASTRIDE 144           // bytes per A row in smem (64 bf16 + 8 pad)
#define NFRAG (12 * 4 * 3)    // k16-chunks x n8-tiles = 144 B-fragments

__device__ __align__(16) float g_emx[BATCH * SEQ * NC];   // 2^em2 (linear emissions)
__device__ __align__(16) uint32_t g_wfrag[NFRAG * 64];    // W bf16, mma-frag order (36KB)
__device__ float g_res[BATCH];

__device__ __forceinline__ float fast_ex2(float x) {
    float y; asm("ex2.approx.ftz.f32 %0, %1;" : "=f"(y) : "f"(x)); return y;
}
__device__ __forceinline__ float fast_lg2(float x) {
    float y; asm("lg2.approx.ftz.f32 %0, %1;" : "=f"(y) : "f"(x)); return y;
}
__device__ __forceinline__ uint32_t smem_u32(const void* p) {
    uint32_t a;
    asm("{ .reg .u64 t; cvta.to.shared.u64 t, %1; cvt.u32.u64 %0, t; }" : "=r"(a) : "l"(p));
    return a;
}

// ---------------------------------------------------------------------------
// Kernel 0: pack W into mma B-fragment order.
// frag f = (chunk*4 + ksub)*3 + nt; lane l; reg h in {0,1}:
//   k = chunk*64 + ksub*16 + (l&3)*2 + h*8 ; n = nt*8 + (l>>2)
//   value = pack_bf16x2( W[k][n], W[k+1][n] )   (0 if n >= 21)
// ---------------------------------------------------------------------------
__global__ void pack_w_kernel(const float* __restrict__ W) {
    int o = blockIdx.x * blockDim.x + threadIdx.x;
    if (o >= NFRAG * 64) return;
    int h    = o & 1;
    int lane = (o >> 1) & 31;
    int f    = o >> 6;
    int nt   = f % 3;
    int kc   = f / 3;
    int k    = (kc >> 2) * 64 + (kc & 3) * 16 + (lane & 3) * 2 + h * 8;
    int n    = nt * 8 + (lane >> 2);
    float w0 = (n < NC) ? W[k * NC + n]       : 0.f;
    float w1 = (n < NC) ? W[(k + 1) * NC + n] : 0.f;
    uint32_t pk;
    asm("cvt.rn.satfinite.bf16x2.f32 %0, %1, %2;" : "=r"(pk) : "f"(w1), "f"(w0));
    g_wfrag[o] = pk;
}

// ---------------------------------------------------------------------------
// Kernel 1: emissions GEMM via mma.sync m16n8k16 bf16 (tensor pipe; tcgen05
// is unavailable on this toolchain's compute_103 target).
// 512 CTAs x 128 thr; warp w owns rows [w*16, w*16+16), all 24 cols.
// A: coalesced fp32->bf16 -> smem -> ldmatrix.x4. B: one LDG.64/frag from
// g_wfrag (L1-hot, coalesced). Double-buffered A, one barrier per chunk.
// ---------------------------------------------------------------------------
__global__ __launch_bounds__(128) void gemm_kernel(
    const float* __restrict__ hidden,
    const float* __restrict__ bias)
{
    __shared__ __align__(16) uint8_t a_sm[2][BM * ASTRIDE];   // 2 x 9216 B

    const int tid  = threadIdx.x;
    const int wid  = tid >> 5;
    const int lane = tid & 31;
    const int row0 = blockIdx.x * BM;

    float acc[3][4];
#pragma unroll
    for (int i = 0; i < 3; i++)
#pragma unroll
        for (int j = 0; j < 4; j++) acc[i][j] = 0.f;

    auto fill = [&](int chunk, int st) {
        const int k0 = chunk * 64;
#pragma unroll
        for (int u = 0; u < 16; u++) {
            int p = tid + u * 128;            // 0..2047
            int r = p >> 5, kp = p & 31;
            float2 hv = *reinterpret_cast<const float2*>(
                hidden + (uint64_t)(row0 + r) * HID + k0 + 2 * kp);
            uint32_t bfx;
            asm("cvt.rn.satfinite.bf16x2.f32 %0, %1, %2;" : "=r"(bfx) : "f"(hv.y), "f"(hv.x));
            *reinterpret_cast<uint32_t*>(a_sm[st] + r * ASTRIDE + kp * 4) = bfx;
        }
    };

    fill(0, 0);
    __syncthreads();

    // ldmatrix per-lane row: tiles (r0-7,k0-7),(r8-15,k0-7),(r0-7,k8-15),(r8-15,k8-15)
    const int rowA = wid * 16 + (lane & 7) + ((lane >> 3) & 1) * 8;
    const int aoff = rowA * ASTRIDE + ((lane >> 4) * 16);

    for (int chunk = 0; chunk < 12; chunk++) {
        if (chunk + 1 < 12) fill(chunk + 1, (chunk + 1) & 1);
        const uint8_t* as = a_sm[chunk & 1];
        const uint32_t abase = smem_u32(as + aoff);
#pragma unroll
        for (int ksub = 0; ksub < 4; ksub++) {
            uint32_t a0, a1, a2, a3;
            asm volatile("ldmatrix.sync.aligned.m8n8.x4.shared.b16 {%0,%1,%2,%3}, [%4];"
                : "=r"(a0), "=r"(a1), "=r"(a2), "=r"(a3)
                : "r"(abase + ksub * 32));
            const int fbase = ((chunk * 4 + ksub) * 3) * 64 + lane * 2;
#pragma unroll
            for (int nt = 0; nt < 3; nt++) {
                uint2 b = *reinterpret_cast<const uint2*>(&g_wfrag[fbase + nt * 64]);
                asm volatile("mma.sync.aligned.m16n8k16.row.col.f32.bf16.bf16.f32 "
                    "{%0,%1,%2,%3}, {%4,%5,%6,%7}, {%8,%9}, {%0,%1,%2,%3};"
                    : "+f"(acc[nt][0]), "+f"(acc[nt][1]), "+f"(acc[nt][2]), "+f"(acc[nt][3])
                    : "r"(a0), "r"(a1), "r"(a2), "r"(a3), "r"(b.x), "r"(b.y));
            }
        }
        __syncthreads();
    }

    // epilogue: frag -> emx -> smem (alias a_sm) -> coalesced store
    float* smf = reinterpret_cast<float*>(a_sm);   // 64*21 floats = 5376 B
    const int r0 = wid * 16 + (lane >> 2);
#pragma unroll
    for (int nt = 0; nt < 3; nt++) {
        int c = nt * 8 + (lane & 3) * 2;
        if (c < NC) {
            float bc = bias[c];
            smf[r0 * NC + c]       = fast_ex2((acc[nt][0] + bc) * L2E);
            smf[(r0 + 8) * NC + c] = fast_ex2((acc[nt][2] + bc) * L2E);
        }
        if (c + 1 < NC) {
            float bc = bias[c + 1];
            smf[r0 * NC + c + 1]       = fast_ex2((acc[nt][1] + bc) * L2E);
            smf[(r0 + 8) * NC + c + 1] = fast_ex2((acc[nt][3] + bc) * L2E);
        }
    }
    __syncthreads();
    {
        float4* dst = reinterpret_cast<float4*>(g_emx + (uint64_t)row0 * NC);
        const float4* src = reinterpret_cast<const float4*>(smf);
        for (int i = tid; i < (BM * NC) / 4; i += 128) dst[i] = src[i];
    }
}

// ---------------------------------------------------------------------------
// Kernel 2: per-batch CRF (R6-proven structure), linear-space scan with
// smem-broadcast alpha; numerator via lg2(emx).
// ---------------------------------------------------------------------------
__global__ __launch_bounds__(128) void crf_kernel(
    const float* __restrict__ start_t,
    const float* __restrict__ end_t,
    const float* __restrict__ trans,
    const int*   __restrict__ labr)
{
    __shared__ __align__(16) float emx_s[SEQ * NC];  // 43008 B
    __shared__ __align__(16) float av[2][24];
    __shared__ float red_f[128];
    __shared__ int   red_i[128];
    __shared__ float s_num2;
    __shared__ int   s_len;

    const int b   = blockIdx.x;
    const int tid = threadIdx.x;
    const float* emx_g = g_emx + b * EM_STRIDE;

    // labels dtype detection (int32 vs int64; reads in-bounds for both)
    int ok = 1;
    for (int t = tid; t < SEQ; t += 128) {
        int v = labr[2 * t + 1];
        if (v != 0 && v != -1) ok = 0;
    }
    int is64 = __syncthreads_and(ok);
    const int lbase = is64 ? b * SEQ * 2 : b * SEQ;
    const int lstep = is64 ? 2 : 1;
#define LAB(t) labr[lbase + (t) * lstep]

    for (int i = tid; i < (SEQ * NC) / 4; i += 128)
        reinterpret_cast<float4*>(emx_s)[i] =
            reinterpret_cast<const float4*>(emx_g)[i];

    // numerator (log2 domain) + valid length (mask is a prefix)
    float p = 0.f;
    int cnt = 0;
    for (int t = tid; t < SEQ; t += 128) {
        int l = LAB(t);
        if (l != -100) {
            cnt++;
            if (t == 0) {
                p += start_t[l] * L2E + fast_lg2(emx_g[l]);
            } else {
                int lp = LAB(t - 1);
                p += fast_lg2(emx_g[t * NC + l]) + trans[lp * NC + l] * L2E;
            }
        }
    }
    red_f[tid] = p;
    red_i[tid] = cnt;
    __syncthreads();
    for (int s = 64; s > 0; s >>= 1) {
        if (tid < s) { red_f[tid] += red_f[tid + s]; red_i[tid] += red_i[tid + s]; }
        __syncthreads();
    }
    if (tid == 0) {
        int len = red_i[0];
        s_len   = len;
        s_num2  = red_f[0] + end_t[LAB(len - 1)] * L2E;
    }
    __syncthreads();

    if (tid < 32) {
        const int lane = tid;
        const int j = lane < NC ? lane : NC - 1;
        float tl[24];
#pragma unroll
        for (int i = 0; i < NC; i++) tl[i] = fast_ex2(trans[i * NC + j] * L2E);
        tl[21] = tl[22] = tl[23] = 0.f;
        const float endx = fast_ex2(end_t[j] * L2E);

        float a = fast_ex2(start_t[j] * L2E) * emx_s[j];
        if (lane < NC)  av[0][lane] = a;
        if (lane >= NC && lane < 24) { av[0][lane] = 0.f; av[1][lane] = 0.f; }
        int offe = 0;
        int buf  = 0;
        const int len = s_len;

        for (int t = 1; t < len; t++) {
            __syncwarp();
            const float4* vp = reinterpret_cast<const float4*>(av[buf]);
            float4 v0 = vp[0], v1 = vp[1], v2 = vp[2],
                   v3 = vp[3], v4 = vp[4], v5 = vp[5];
            float emn = emx_s[t * NC + j];
            int   e     = ((__float_as_int(v0.x) >> 23) & 255) - 127;
            float sclem = __int_as_float((127 - e) << 23) * emn;  // exact 2^-e
            offe += e;

            float s0 = v0.x * tl[0],  s1 = v0.y * tl[1],  s2 = v0.z * tl[2];
            float s3 = v0.w * tl[3],  s4 = v1.x * tl[4],  s5 = v1.y * tl[5];
            s0 += v1.z * tl[6];   s1 += v1.w * tl[7];   s2 += v2.x * tl[8];
            s3 += v2.y * tl[9];   s4 += v2.z * tl[10];  s5 += v2.w * tl[11];
            s0 += v3.x * tl[12];  s1 += v3.y * tl[13];  s2 += v3.z * tl[14];
            s3 += v3.w * tl[15];  s4 += v4.x * tl[16];  s5 += v4.y * tl[17];
            s0 += v4.z * tl[18];  s1 += v4.w * tl[19];  s2 += v5.x * tl[20];
            s3 += v5.y * tl[21];  s4 += v5.z * tl[22];  s5 += v5.w * tl[23];

            a = (((s0 + s1) + (s2 + s3)) + (s4 + s5)) * sclem;
            buf ^= 1;
            if (lane < NC) av[buf][lane] = a;
        }
        __syncwarp();

        float ex = (lane < NC) ? a * endx : 0.f;
#pragma unroll
        for (int d = 16; d > 0; d >>= 1)
            ex += __shfl_xor_sync(0xffffffffu, ex, d);
        if (lane == 0)
            g_res[b] = (float)offe + fast_lg2(ex) - s_num2;
    }
#undef LAB
}

// ---------------------------------------------------------------------------
__global__ void finish_kernel(float* __restrict__ out) {
    int tid = threadIdx.x;           // 32 threads
    float v = g_res[tid] + g_res[tid + 32];
#pragma unroll
    for (int d = 16; d > 0; d >>= 1)
        v += __shfl_xor_sync(0xffffffffu, v, d);
    if (tid == 0) out[0] = v * (1.0f / (64.0f * L2E));
}

// ---------------------------------------------------------------------------
extern "C" void kernel_launch(void* const* d_in, const int* in_sizes, int n_in,
                              void* d_out, int out_size)
{
    const float* hidden = nullptr;
    const float* W      = nullptr;
    const float* trans  = nullptr;
    const int*   labels = nullptr;
    const float* small[3] = {nullptr, nullptr, nullptr};
    int nsmall = 0;

    for (int i = 0; i < n_in; i++) {
        switch (in_sizes[i]) {
            case BATCH * SEQ * HID: hidden = (const float*)d_in[i]; break;
            case HID * NC:          W      = (const float*)d_in[i]; break;
            case NC * NC:           trans  = (const float*)d_in[i]; break;
            case BATCH * SEQ:       labels = (const int*)d_in[i];   break;
            case NC: if (nsmall < 3) small[nsmall++] = (const float*)d_in[i]; break;
            default: break;
        }
    }
    const float* bias    = small[0];
    const float* start_t = small[1];
    const float* end_t   = small[2];

    pack_w_kernel<<<(NFRAG * 64 + 255) / 256, 256>>>(W);
    gemm_kernel<<<512, 128>>>(hidden, bias);
    crf_kernel<<<BATCH, 128>>>(start_t, end_t, trans, labels);
    finish_kernel<<<1, 32>>>((float*)d_out);
}

// round 11
// speedup vs baseline: 3.6600x; 1.1830x over previous
#include <cuda_runtime.h>
#include <cuda_bf16.h>
#include <cstdint>

#define L2E 1.4426950408889634f
#define BATCH 64
#define SEQ 512
#define HID 768
#define NC 21
#define EM_STRIDE (SEQ * NC)

#define BM 64
#define ASTRIDE 144           // bytes per A row in smem (64 bf16 + 8 pad)
#define NFRAG (12 * 4 * 3)    // k16-chunks x n8-tiles = 144 B-fragments

__device__ __align__(16) float g_emx[BATCH * SEQ * NC];   // 2^em2 (linear emissions)
__device__ __align__(16) uint32_t g_wfrag[NFRAG * 64];    // W bf16, mma-frag order
__device__ float g_res[BATCH];
__device__ int g_bcnt[BATCH];   // per-batch gemm-CTA arrival counters (self-reset)
__device__ int g_done;          // scans-finished counter (self-reset)

__device__ __forceinline__ float fast_ex2(float x) {
    float y; asm("ex2.approx.ftz.f32 %0, %1;" : "=f"(y) : "f"(x)); return y;
}
__device__ __forceinline__ float fast_lg2(float x) {
    float y; asm("lg2.approx.ftz.f32 %0, %1;" : "=f"(y) : "f"(x)); return y;
}
__device__ __forceinline__ uint32_t smem_u32(const void* p) {
    uint32_t a;
    asm("{ .reg .u64 t; cvta.to.shared.u64 t, %1; cvt.u32.u64 %0, t; }" : "=r"(a) : "l"(p));
    return a;
}

// ---------------------------------------------------------------------------
// Kernel 0: pack W into mma B-fragment order.
// frag f = (chunk*4 + ksub)*3 + nt; lane l; reg h in {0,1}:
//   k = chunk*64 + ksub*16 + (l&3)*2 + h*8 ; n = nt*8 + (l>>2)
// ---------------------------------------------------------------------------
__global__ void pack_w_kernel(const float* __restrict__ W) {
    int o = blockIdx.x * blockDim.x + threadIdx.x;
    if (o >= NFRAG * 64) return;
    int h    = o & 1;
    int lane = (o >> 1) & 31;
    int f    = o >> 6;
    int nt   = f % 3;
    int kc   = f / 3;
    int k    = (kc >> 2) * 64 + (kc & 3) * 16 + (lane & 3) * 2 + h * 8;
    int n    = nt * 8 + (lane >> 2);
    float w0 = (n < NC) ? W[k * NC + n]       : 0.f;
    float w1 = (n < NC) ? W[(k + 1) * NC + n] : 0.f;
    uint32_t pk;
    asm("cvt.rn.satfinite.bf16x2.f32 %0, %1, %2;" : "=r"(pk) : "f"(w1), "f"(w0));
    g_wfrag[o] = pk;
}

// ---------------------------------------------------------------------------
// Fused kernel: gemm tile (mma.sync bf16) -> per-batch handoff counter ->
// the 8th-arriving CTA of each batch runs that batch's CRF scan inline ->
// the 64th-finishing scan does the final loss reduction.
// smem: 44KB union (gemm A tiles+epilogue | scan emission staging+reductions).
// ---------------------------------------------------------------------------
#define USM_BYTES 44224
__global__ __launch_bounds__(128) void fused_kernel(
    const float* __restrict__ hidden,
    const float* __restrict__ bias,
    const float* __restrict__ start_t,
    const float* __restrict__ end_t,
    const float* __restrict__ trans,
    const int*   __restrict__ labr,
    float* __restrict__ out)
{
    __shared__ __align__(1024) uint8_t usm[USM_BYTES];
    __shared__ float s_num2;
    __shared__ int   s_len, s_flag, s_last;

    const int tid  = threadIdx.x;
    const int wid  = tid >> 5;
    const int lane = tid & 31;
    const int row0 = blockIdx.x * BM;
    const int batch = blockIdx.x >> 3;   // 8 CTAs per batch

    // ---------------- GEMM phase ----------------
    uint8_t (*a_sm)[BM * ASTRIDE] =
        reinterpret_cast<uint8_t(*)[BM * ASTRIDE]>(usm);   // 2 x 9216 B

    float acc[3][4];
#pragma unroll
    for (int i = 0; i < 3; i++)
#pragma unroll
        for (int j = 0; j < 4; j++) acc[i][j] = 0.f;

    auto fill = [&](int chunk, int st) {
        const int k0 = chunk * 64;
#pragma unroll
        for (int u = 0; u < 16; u++) {
            int p = tid + u * 128;
            int r = p >> 5, kp = p & 31;
            float2 hv = *reinterpret_cast<const float2*>(
                hidden + (uint64_t)(row0 + r) * HID + k0 + 2 * kp);
            uint32_t bfx;
            asm("cvt.rn.satfinite.bf16x2.f32 %0, %1, %2;" : "=r"(bfx) : "f"(hv.y), "f"(hv.x));
            *reinterpret_cast<uint32_t*>(a_sm[st] + r * ASTRIDE + kp * 4) = bfx;
        }
    };

    fill(0, 0);
    __syncthreads();

    const int rowA = wid * 16 + (lane & 7) + ((lane >> 3) & 1) * 8;
    const int aoff = rowA * ASTRIDE + ((lane >> 4) * 16);

    for (int chunk = 0; chunk < 12; chunk++) {
        if (chunk + 1 < 12) fill(chunk + 1, (chunk + 1) & 1);
        const uint32_t abase = smem_u32(a_sm[chunk & 1] + aoff);
#pragma unroll
        for (int ksub = 0; ksub < 4; ksub++) {
            uint32_t a0, a1, a2, a3;
            asm volatile("ldmatrix.sync.aligned.m8n8.x4.shared.b16 {%0,%1,%2,%3}, [%4];"
                : "=r"(a0), "=r"(a1), "=r"(a2), "=r"(a3)
                : "r"(abase + ksub * 32));
            const int fbase = ((chunk * 4 + ksub) * 3) * 64 + lane * 2;
#pragma unroll
            for (int nt = 0; nt < 3; nt++) {
                uint2 b = *reinterpret_cast<const uint2*>(&g_wfrag[fbase + nt * 64]);
                asm volatile("mma.sync.aligned.m16n8k16.row.col.f32.bf16.bf16.f32 "
                    "{%0,%1,%2,%3}, {%4,%5,%6,%7}, {%8,%9}, {%0,%1,%2,%3};"
                    : "+f"(acc[nt][0]), "+f"(acc[nt][1]), "+f"(acc[nt][2]), "+f"(acc[nt][3])
                    : "r"(a0), "r"(a1), "r"(a2), "r"(a3), "r"(b.x), "r"(b.y));
            }
        }
        __syncthreads();
    }

    // epilogue: frag -> emx -> smem (alias) -> coalesced store
    {
        float* smf = reinterpret_cast<float*>(usm);   // 64*21 floats
        const int r0 = wid * 16 + (lane >> 2);
#pragma unroll
        for (int nt = 0; nt < 3; nt++) {
            int c = nt * 8 + (lane & 3) * 2;
            if (c < NC) {
                float bc = bias[c];
                smf[r0 * NC + c]       = fast_ex2((acc[nt][0] + bc) * L2E);
                smf[(r0 + 8) * NC + c] = fast_ex2((acc[nt][2] + bc) * L2E);
            }
            if (c + 1 < NC) {
                float bc = bias[c + 1];
                smf[r0 * NC + c + 1]       = fast_ex2((acc[nt][1] + bc) * L2E);
                smf[(r0 + 8) * NC + c + 1] = fast_ex2((acc[nt][3] + bc) * L2E);
            }
        }
        __syncthreads();
        float4* dst = reinterpret_cast<float4*>(g_emx + (uint64_t)row0 * NC);
        const float4* src = reinterpret_cast<const float4*>(smf);
        for (int i = tid; i < (BM * NC) / 4; i += 128) dst[i] = src[i];
    }

    // ---------------- handoff: 8th arriver scans this batch ----------------
    __threadfence();
    if (tid == 0) s_flag = (atomicAdd(&g_bcnt[batch], 1) == 7);
    __syncthreads();
    if (!s_flag) return;

    // ---------------- CRF scan phase (this CTA only) ----------------
    float* emx_s      = reinterpret_cast<float*>(usm);            // 43008 B
    float (*av)[24]   = reinterpret_cast<float(*)[24]>(usm + 43008);
    float* red_f      = reinterpret_cast<float*>(usm + 43200);    // 512 B
    int*   red_i      = reinterpret_cast<int*>(usm + 43712);      // 512 B

    const float* emx_g = g_emx + batch * EM_STRIDE;

    // labels dtype detection (int32 vs int64; reads in-bounds for both)
    int ok = 1;
    for (int t = tid; t < SEQ; t += 128) {
        int v = labr[2 * t + 1];
        if (v != 0 && v != -1) ok = 0;
    }
    __syncthreads();   // also separates epilogue smem use from scan reuse
    int is64 = __syncthreads_and(ok);
    const int lbase = is64 ? batch * SEQ * 2 : batch * SEQ;
    const int lstep = is64 ? 2 : 1;
#define LAB(t) labr[lbase + (t) * lstep]

    for (int i = tid; i < (SEQ * NC) / 4; i += 128)
        reinterpret_cast<float4*>(emx_s)[i] =
            reinterpret_cast<const float4*>(emx_g)[i];

    // numerator (log2 domain) + valid length (mask is a prefix)
    float p = 0.f;
    int cnt = 0;
    for (int t = tid; t < SEQ; t += 128) {
        int l = LAB(t);
        if (l != -100) {
            cnt++;
            if (t == 0) {
                p += start_t[l] * L2E + fast_lg2(emx_g[l]);
            } else {
                int lp = LAB(t - 1);
                p += fast_lg2(emx_g[t * NC + l]) + trans[lp * NC + l] * L2E;
            }
        }
    }
    red_f[tid] = p;
    red_i[tid] = cnt;
    __syncthreads();
    for (int s = 64; s > 0; s >>= 1) {
        if (tid < s) { red_f[tid] += red_f[tid + s]; red_i[tid] += red_i[tid + s]; }
        __syncthreads();
    }
    if (tid == 0) {
        int len = red_i[0];
        s_len   = len;
        s_num2  = red_f[0] + end_t[LAB(len - 1)] * L2E;
    }
    __syncthreads();

    if (tid < 32) {
        const int j = lane < NC ? lane : NC - 1;
        float tl[24];
#pragma unroll
        for (int i = 0; i < NC; i++) tl[i] = fast_ex2(trans[i * NC + j] * L2E);
        tl[21] = tl[22] = tl[23] = 0.f;
        const float endx = fast_ex2(end_t[j] * L2E);

        float a = fast_ex2(start_t[j] * L2E) * emx_s[j];
        if (lane < NC)  av[0][lane] = a;
        if (lane >= NC && lane < 24) { av[0][lane] = 0.f; av[1][lane] = 0.f; }
        int offe = 0;
        int buf  = 0;
        const int len = s_len;

        for (int t = 1; t < len; t++) {
            __syncwarp();
            const float4* vp = reinterpret_cast<const float4*>(av[buf]);
            float4 v0 = vp[0], v1 = vp[1], v2 = vp[2],
                   v3 = vp[3], v4 = vp[4], v5 = vp[5];
            float emn = emx_s[t * NC + j];
            int   e     = ((__float_as_int(v0.x) >> 23) & 255) - 127;
            float sclem = __int_as_float((127 - e) << 23) * emn;  // exact 2^-e
            offe += e;

            float s0 = v0.x * tl[0],  s1 = v0.y * tl[1],  s2 = v0.z * tl[2];
            float s3 = v0.w * tl[3],  s4 = v1.x * tl[4],  s5 = v1.y * tl[5];
            s0 += v1.z * tl[6];   s1 += v1.w * tl[7];   s2 += v2.x * tl[8];
            s3 += v2.y * tl[9];   s4 += v2.z * tl[10];  s5 += v2.w * tl[11];
            s0 += v3.x * tl[12];  s1 += v3.y * tl[13];  s2 += v3.z * tl[14];
            s3 += v3.w * tl[15];  s4 += v4.x * tl[16];  s5 += v4.y * tl[17];
            s0 += v4.z * tl[18];  s1 += v4.w * tl[19];  s2 += v5.x * tl[20];
            s3 += v5.y * tl[21];  s4 += v5.z * tl[22];  s5 += v5.w * tl[23];

            a = (((s0 + s1) + (s2 + s3)) + (s4 + s5)) * sclem;
            buf ^= 1;
            if (lane < NC) av[buf][lane] = a;
        }
        __syncwarp();

        float ex = (lane < NC) ? a * endx : 0.f;
#pragma unroll
        for (int d = 16; d > 0; d >>= 1)
            ex += __shfl_xor_sync(0xffffffffu, ex, d);
        if (lane == 0)
            g_res[batch] = (float)offe + fast_lg2(ex) - s_num2;
    }
#undef LAB

    // ---------------- final loss: 64th scanner reduces ----------------
    __syncthreads();
    __threadfence();
    if (tid == 0) {
        g_bcnt[batch] = 0;                       // reset for graph replay
        s_last = (atomicAdd(&g_done, 1) == BATCH - 1);
    }
    __syncthreads();
    if (s_last && tid < 32) {
        float v = g_res[tid] + g_res[tid + 32];
#pragma unroll
        for (int d = 16; d > 0; d >>= 1)
            v += __shfl_xor_sync(0xffffffffu, v, d);
        if (tid == 0) {
            out[0] = v * (1.0f / (64.0f * L2E));
            g_done = 0;                          // reset for graph replay
        }
    }
}

// ---------------------------------------------------------------------------
extern "C" void kernel_launch(void* const* d_in, const int* in_sizes, int n_in,
                              void* d_out, int out_size)
{
    const float* hidden = nullptr;
    const float* W      = nullptr;
    const float* trans  = nullptr;
    const int*   labels = nullptr;
    const float* small[3] = {nullptr, nullptr, nullptr};
    int nsmall = 0;

    for (int i = 0; i < n_in; i++) {
        switch (in_sizes[i]) {
            case BATCH * SEQ * HID: hidden = (const float*)d_in[i]; break;
            case HID * NC:          W      = (const float*)d_in[i]; break;
            case NC * NC:           trans  = (const float*)d_in[i]; break;
            case BATCH * SEQ:       labels = (const int*)d_in[i];   break;
            case NC: if (nsmall < 3) small[nsmall++] = (const float*)d_in[i]; break;
            default: break;
        }
    }
    const float* bias    = small[0];
    const float* start_t = small[1];
    const float* end_t   = small[2];

    pack_w_kernel<<<(NFRAG * 64 + 255) / 256, 256>>>(W);
    fused_kernel<<<512, 128>>>(hidden, bias, start_t, end_t, trans, labels,
                               (float*)d_out);
}